// round 4
// baseline (speedup 1.0000x reference)
#include <cuda_runtime.h>
#include <cuda_fp16.h>
#include <cuda_bf16.h>
#include <cstdint>

// Problem dims
#define B_ 1024
#define C_ 65536
#define D_ 512

// ---------------- scratch (device globals; no runtime allocation) ----------------
__device__ int8_t   g_xq[(size_t)B_ * D_];        // 0.5 MB quantized x
__device__ int8_t   g_kq[(size_t)C_ * D_];        // 32 MB quantized keys
__device__ float    g_sx[B_];                     // per-row scales
__device__ float    g_sk[C_];
__device__ __half   g_ws[(size_t)B_ * C_];        // 128 MB approx ws (fp16)
__device__ unsigned g_rowmax[B_];                 // order-encoded fp32 row max

#define SW128(o)   ((o) ^ (((o) >> 3) & 0x70))

__device__ __forceinline__ uint32_t smem_u32(const void* p) {
    uint32_t a;
    asm("{ .reg .u64 t; cvta.to.shared.u64 t, %1; cvt.u32.u64 %0, t; }" : "=r"(a) : "l"(p));
    return a;
}

__device__ __forceinline__ void ldsm4(uint32_t& r0, uint32_t& r1, uint32_t& r2, uint32_t& r3, uint32_t a) {
    asm volatile("ldmatrix.sync.aligned.m8n8.x4.shared.b16 {%0,%1,%2,%3}, [%4];"
                 : "=r"(r0), "=r"(r1), "=r"(r2), "=r"(r3) : "r"(a));
}

__device__ __forceinline__ void imma16832(int* c, const uint32_t* a, uint32_t b0, uint32_t b1) {
    asm volatile(
        "mma.sync.aligned.m16n8k32.row.col.s32.s8.s8.s32 "
        "{%0,%1,%2,%3}, {%4,%5,%6,%7}, {%8,%9}, {%0,%1,%2,%3};"
        : "+r"(c[0]), "+r"(c[1]), "+r"(c[2]), "+r"(c[3])
        : "r"(a[0]), "r"(a[1]), "r"(a[2]), "r"(a[3]), "r"(b0), "r"(b1));
}

// order-preserving float<->uint encoding for atomicMax
__device__ __forceinline__ unsigned fenc(float f) {
    unsigned u = __float_as_uint(f);
    return (u & 0x80000000u) ? ~u : (u | 0x80000000u);
}
__device__ __forceinline__ float fdec(unsigned u) {
    return (u & 0x80000000u) ? __uint_as_float(u & 0x7fffffffu) : __uint_as_float(~u);
}

// ---------------- kernel 1: fp32 -> int8 per-row quantize (warp per row) ----------------
__global__ void __launch_bounds__(256) quant_kernel(const float* __restrict__ x,
                                                    const float* __restrict__ keys) {
    int gw = (int)((blockIdx.x * 256 + threadIdx.x) >> 5);
    int lane = threadIdx.x & 31;
    if (gw >= B_ + C_) return;
    bool isx = gw < B_;
    const float4* s4 = (const float4*)(isx ? x + (size_t)gw * D_
                                           : keys + (size_t)(gw - B_) * D_);
    float4 v[4];
    float m = 0.f;
    #pragma unroll
    for (int j = 0; j < 4; j++) {
        v[j] = s4[lane + 32 * j];
        m = fmaxf(m, fmaxf(fmaxf(fabsf(v[j].x), fabsf(v[j].y)),
                           fmaxf(fabsf(v[j].z), fabsf(v[j].w))));
    }
    #pragma unroll
    for (int o = 16; o; o >>= 1) m = fmaxf(m, __shfl_xor_sync(0xffffffffu, m, o));
    m = fmaxf(m, 1e-30f);
    float inv = 127.f / m;
    uint32_t* dst = (uint32_t*)(isx ? g_xq + (size_t)gw * D_
                                    : g_kq + (size_t)(gw - B_) * D_);
    #pragma unroll
    for (int j = 0; j < 4; j++) {
        int a0 = __float2int_rn(v[j].x * inv);
        int a1 = __float2int_rn(v[j].y * inv);
        int a2 = __float2int_rn(v[j].z * inv);
        int a3 = __float2int_rn(v[j].w * inv);
        uint32_t p = (uint32_t)(a0 & 0xff) | ((uint32_t)(a1 & 0xff) << 8) |
                     ((uint32_t)(a2 & 0xff) << 16) | ((uint32_t)(a3 & 0xff) << 24);
        dst[lane + 32 * j] = p;
    }
    if (lane == 0) {
        float sc = m / 127.f;
        if (isx) { g_sx[gw] = sc; g_rowmax[gw] = 0u; }
        else g_sk[gw - B_] = sc;
    }
}

// ---------------- kernel 2: int8 IMMA GEMM ----------------------------------------
// CTA tile 128x128, K=512 in 4 chunks of 128 int8 (128B rows). 8 warps 4(M)x2(N).
// 3-buffer LDG->STS pipeline, ONE barrier per chunk, 2 CTAs/SM.
#define KC 128
#define CHUNK_A 16384                // 128 rows * 128 B
#define STAGE_BYTES 32768            // A + B
#define NSTAGE 3
#define SMEM_ALLOC (NSTAGE * STAGE_BYTES + 1024)

__device__ __forceinline__ void ldg_chunk(uint4* r, int q0, int c0, int k0, int tid) {
    const int8_t* Ag = g_xq + (size_t)q0 * D_ + k0;
    const int8_t* Bg = g_kq + (size_t)c0 * D_ + k0;
    #pragma unroll
    for (int j = 0; j < 4; j++) {
        int u = j * 256 + tid;
        r[j] = *(const uint4*)(Ag + (size_t)(u >> 3) * D_ + (u & 7) * 16);
    }
    #pragma unroll
    for (int j = 0; j < 4; j++) {
        int u = j * 256 + tid;
        r[4 + j] = *(const uint4*)(Bg + (size_t)(u >> 3) * D_ + (u & 7) * 16);
    }
}

__device__ __forceinline__ void sts_chunk(char* stage, const uint4* r, int tid) {
    #pragma unroll
    for (int j = 0; j < 4; j++) {
        int u = j * 256 + tid;
        uint32_t off = SW128((uint32_t)((u >> 3) * 128 + (u & 7) * 16));
        *(uint4*)(stage + off) = r[j];
    }
    #pragma unroll
    for (int j = 0; j < 4; j++) {
        int u = j * 256 + tid;
        uint32_t off = SW128((uint32_t)((u >> 3) * 128 + (u & 7) * 16));
        *(uint4*)(stage + CHUNK_A + off) = r[4 + j];
    }
}

__global__ void __launch_bounds__(256, 2) gemm_kernel(const float* __restrict__ logt) {
    extern __shared__ char smraw[];
    __shared__ float skS[128];
    uint32_t sbr = smem_u32(smraw);
    uint32_t sb = (sbr + 1023u) & ~1023u;
    char* smem = smraw + (sb - sbr);

    int tid = threadIdx.x;
    int wid = tid >> 5, lane = tid & 31;
    int wm = wid >> 1, wn = wid & 1;
    int mt = blockIdx.x & 7;
    int nt = blockIdx.x >> 3;
    int q0 = mt * 128, c0 = nt * 128;

    if (tid < 128) skS[tid] = g_sk[c0 + tid];

    int acc[2][8][4];
    #pragma unroll
    for (int t = 0; t < 2; t++)
        #pragma unroll
        for (int n = 0; n < 8; n++)
            #pragma unroll
            for (int r = 0; r < 4; r++) acc[t][n][r] = 0;

    uint4 rg[8];
    // prologue: chunks 0,1 into stages 0,1
    ldg_chunk(rg, q0, c0, 0, tid);
    sts_chunk(smem, rg, tid);
    ldg_chunk(rg, q0, c0, KC, tid);
    sts_chunk(smem + STAGE_BYTES, rg, tid);
    __syncthreads();

    // ldmatrix lane address components (int8, 128B rows)
    int aRow = wm * 32 + ((lane >> 3) & 1) * 8 + (lane & 7);
    uint32_t aColB = (uint32_t)((lane >> 4) * 16);
    int bm = lane >> 3;
    int bRowIn = (bm >> 1) * 8 + (lane & 7);
    uint32_t bColB = (uint32_t)((bm & 1) * 16);

    #pragma unroll
    for (int i = 0; i < 4; i++) {
        if (i < 2) ldg_chunk(rg, q0, c0, (i + 2) * KC, tid);

        uint32_t bufA = sb + (i % NSTAGE) * STAGE_BYTES;
        uint32_t bufB = bufA + CHUNK_A;

        #pragma unroll
        for (int half = 0; half < 2; half++) {
            #pragma unroll
            for (int k2 = 0; k2 < 2; k2++) {
                int ks = half * 2 + k2;
                uint32_t kb = (uint32_t)(ks * 32);
                uint32_t a[2][4];
                #pragma unroll
                for (int t = 0; t < 2; t++) {
                    uint32_t off = (uint32_t)((aRow + t * 16) * 128) + kb + aColB;
                    ldsm4(a[t][0], a[t][1], a[t][2], a[t][3], bufA + SW128(off));
                }
                #pragma unroll
                for (int p = 0; p < 4; p++) {
                    uint32_t b0, b1, b2, b3;
                    uint32_t off = (uint32_t)((wn * 64 + p * 16 + bRowIn) * 128) + kb + bColB;
                    ldsm4(b0, b1, b2, b3, bufB + SW128(off));
                    #pragma unroll
                    for (int t = 0; t < 2; t++) {
                        imma16832(acc[t][p * 2 + 0], a[t], b0, b1);
                        imma16832(acc[t][p * 2 + 1], a[t], b2, b3);
                    }
                }
            }
            // land the prefetched chunk between the two compute halves
            if (half == 0 && i < 2)
                sts_chunk(smem + ((i + 2) % NSTAGE) * STAGE_BYTES, rg, tid);
        }
        __syncthreads();
    }

    // epilogue: score = acc * sx[q]*sk[c]*inv_t; fp16 store + encoded rowmax atomics
    float inv_t = __expf(-logt[0]);
    int g = lane >> 2, tig = lane & 3;
    #pragma unroll
    for (int t = 0; t < 2; t++) {
        #pragma unroll
        for (int h = 0; h < 2; h++) {
            int q = q0 + wm * 32 + t * 16 + h * 8 + g;
            float rowScale = g_sx[q] * inv_t;
            __half* dst = g_ws + (size_t)q * C_ + c0 + wn * 64;
            float lmax = -3.4e38f;
            #pragma unroll
            for (int n = 0; n < 8; n++) {
                int cL = wn * 64 + n * 8 + tig * 2;
                float v0 = (float)acc[t][n][h * 2 + 0] * rowScale * skS[cL + 0];
                float v1 = (float)acc[t][n][h * 2 + 1] * rowScale * skS[cL + 1];
                lmax = fmaxf(lmax, fmaxf(v0, v1));
                *(__half2*)(dst + n * 8 + tig * 2) = __floats2half2_rn(v0, v1);
            }
            lmax = fmaxf(lmax, __shfl_xor_sync(0xffffffffu, lmax, 1));
            lmax = fmaxf(lmax, __shfl_xor_sync(0xffffffffu, lmax, 2));
            if (tig == 0) atomicMax(&g_rowmax[q], fenc(lmax));
        }
    }
}

// ---------------- kernel 3: select + exact fp32 softmax + gather ----------------
#define CAP 4096
__global__ void __launch_bounds__(256) sel_kernel(
    const float* __restrict__ x, const float* __restrict__ keys,
    const float* __restrict__ values, const float* __restrict__ logt,
    float* __restrict__ out)
{
    __shared__ float xs[D_];
    __shared__ int   cidx[CAP];
    __shared__ float cw[CAP];
    __shared__ float red[256];
    __shared__ int   cnt;

    int q = blockIdx.x;
    int tid = threadIdx.x;
    float inv_t = __expf(-logt[0]);

    for (int d = tid; d < D_; d += 256) xs[d] = x[(size_t)q * D_ + d];
    if (tid == 0) cnt = 0;
    __syncthreads();

    float mx = fdec(g_rowmax[q]);
    // 16.5 softmax tail + fp16 storage + int8 quant GEMM error (in ws units)
    float thr = mx - (16.5f + 0.001f * fabsf(mx) + 2.2f * inv_t);

    const uint4* wrow = (const uint4*)(g_ws + (size_t)q * C_);
    #pragma unroll 1
    for (int j = 0; j < 32; j++) {
        int idx4 = j * 256 + tid;
        union { uint4 v; __half2 h[4]; } u;
        u.v = __ldg(wrow + idx4);
        int cbase = idx4 * 8;
        #pragma unroll
        for (int e = 0; e < 4; e++) {
            float f0 = __low2float(u.h[e]);
            float f1 = __high2float(u.h[e]);
            if (f0 > thr) { int p = atomicAdd(&cnt, 1); if (p < CAP) cidx[p] = cbase + e * 2; }
            if (f1 > thr) { int p = atomicAdd(&cnt, 1); if (p < CAP) cidx[p] = cbase + e * 2 + 1; }
        }
    }
    __syncthreads();
    int n = min(cnt, CAP);

    // deterministic order (typical n ~ 50)
    if (tid == 0 && n <= 1024) {
        for (int a = 1; a < n; a++) {
            int key = cidx[a]; int bb = a - 1;
            while (bb >= 0 && cidx[bb] > key) { cidx[bb + 1] = cidx[bb]; bb--; }
            cidx[bb + 1] = key;
        }
    }
    __syncthreads();

    // exact fp32 ws for selected candidates (one warp per candidate)
    int w = tid >> 5, lane = tid & 31;
    for (int i = w; i < n; i += 8) {
        const float* kr = keys + (size_t)cidx[i] * D_;
        float s = 0.f;
        #pragma unroll
        for (int kk = 0; kk < 16; kk++) s += xs[lane + kk * 32] * __ldg(kr + lane + kk * 32);
        #pragma unroll
        for (int o = 16; o; o >>= 1) s += __shfl_xor_sync(0xffffffffu, s, o);
        if (lane == 0) cw[i] = s * inv_t;
    }
    __syncthreads();

    // exact max over selected
    float lm = -3.4e38f;
    for (int i = tid; i < n; i += 256) lm = fmaxf(lm, cw[i]);
    red[tid] = lm; __syncthreads();
    for (int s2 = 128; s2; s2 >>= 1) { if (tid < s2) red[tid] = fmaxf(red[tid], red[tid + s2]); __syncthreads(); }
    float m = red[0]; __syncthreads();

    // exp + sum
    float ls = 0.f;
    for (int i = tid; i < n; i += 256) { float e = __expf(cw[i] - m); cw[i] = e; ls += e; }
    red[tid] = ls; __syncthreads();
    for (int s2 = 128; s2; s2 >>= 1) { if (tid < s2) red[tid] += red[tid + s2]; __syncthreads(); }
    float invS = 1.0f / red[0]; __syncthreads();

    // weighted gather of values
    float a0 = 0.f, a1 = 0.f;
    int d0 = tid, d1 = tid + 256;
    #pragma unroll 4
    for (int i = 0; i < n; i++) {
        float wv = cw[i];
        const float* vr = values + (size_t)cidx[i] * D_;
        a0 += wv * __ldg(vr + d0);
        a1 += wv * __ldg(vr + d1);
    }
    out[(size_t)q * D_ + d0] = a0 * invS;
    out[(size_t)q * D_ + d1] = a1 * invS;
}

// ---------------- launch ----------------
extern "C" void kernel_launch(void* const* d_in, const int* in_sizes, int n_in,
                              void* d_out, int out_size) {
    const float* x      = (const float*)d_in[0];
    const float* keys   = (const float*)d_in[1];
    const float* values = (const float*)d_in[2];
    const float* logt   = (const float*)d_in[3];
    float* out = (float*)d_out;

    static bool attr_done = false;
    if (!attr_done) {
        cudaFuncSetAttribute(gemm_kernel, cudaFuncAttributeMaxDynamicSharedMemorySize, SMEM_ALLOC);
        attr_done = true;
    }

    quant_kernel<<<(B_ + C_ + 7) / 8, 256>>>(x, keys);
    gemm_kernel<<<(B_ / 128) * (C_ / 128), 256, SMEM_ALLOC>>>(logt);
    sel_kernel<<<B_, 256>>>(x, keys, values, logt, out);
}

// round 5
// speedup vs baseline: 1.7725x; 1.7725x over previous
#include <cuda_runtime.h>
#include <cuda_fp16.h>
#include <cuda_bf16.h>
#include <cstdint>

// Problem dims
#define B_ 1024
#define C_ 65536
#define D_ 512

// ---------------- scratch (device globals; no runtime allocation) ----------------
__device__ __half   g_xh[(size_t)B_ * D_];        // 1 MB fp16 x
__device__ __half   g_kh[(size_t)C_ * D_];        // 64 MB fp16 keys
__device__ __half   g_ws[(size_t)B_ * C_];        // 128 MB approx ws (fp16)
__device__ unsigned g_rowmax[B_];                 // order-encoded fp32 row max

#define SW128(o)   ((o) ^ (((o) >> 3) & 0x70))

__device__ __forceinline__ uint32_t smem_u32(const void* p) {
    uint32_t a;
    asm("{ .reg .u64 t; cvta.to.shared.u64 t, %1; cvt.u32.u64 %0, t; }" : "=r"(a) : "l"(p));
    return a;
}

__device__ __forceinline__ void ldsm4(uint32_t& r0, uint32_t& r1, uint32_t& r2, uint32_t& r3, uint32_t a) {
    asm volatile("ldmatrix.sync.aligned.m8n8.x4.shared.b16 {%0,%1,%2,%3}, [%4];"
                 : "=r"(r0), "=r"(r1), "=r"(r2), "=r"(r3) : "r"(a));
}

// fp16 inputs, fp16 accumulators (2 regs = 4 halves per thread)
__device__ __forceinline__ void mma16816h(uint32_t* c, const uint32_t* a, uint32_t b0, uint32_t b1) {
    asm volatile(
        "mma.sync.aligned.m16n8k16.row.col.f16.f16.f16.f16 "
        "{%0,%1}, {%2,%3,%4,%5}, {%6,%7}, {%0,%1};"
        : "+r"(c[0]), "+r"(c[1])
        : "r"(a[0]), "r"(a[1]), "r"(a[2]), "r"(a[3]), "r"(b0), "r"(b1));
}

// order-preserving float<->uint encoding for atomicMax
__device__ __forceinline__ unsigned fenc(float f) {
    unsigned u = __float_as_uint(f);
    return (u & 0x80000000u) ? ~u : (u | 0x80000000u);
}
__device__ __forceinline__ float fdec(unsigned u) {
    return (u & 0x80000000u) ? __uint_as_float(u & 0x7fffffffu) : __uint_as_float(~u);
}

// ---------------- kernel 1: fp32 -> fp16 convert + rowmax init ----------------
__global__ void conv_kernel(const float* __restrict__ x, const float* __restrict__ keys) {
    size_t i4 = (size_t)blockIdx.x * blockDim.x + threadIdx.x;
    const size_t NX4 = (size_t)B_ * D_ / 4;   // 131072
    const size_t NK4 = (size_t)C_ * D_ / 4;   // 8388608
    if (i4 < NX4) {
        float4 v = ((const float4*)x)[i4];
        __half2 a = __floats2half2_rn(v.x, v.y);
        __half2 b = __floats2half2_rn(v.z, v.w);
        uint2 o; o.x = *(const unsigned*)&a; o.y = *(const unsigned*)&b;
        ((uint2*)g_xh)[i4] = o;
    } else if (i4 < NX4 + NK4) {
        size_t j = i4 - NX4;
        float4 v = ((const float4*)keys)[j];
        __half2 a = __floats2half2_rn(v.x, v.y);
        __half2 b = __floats2half2_rn(v.z, v.w);
        uint2 o; o.x = *(const unsigned*)&a; o.y = *(const unsigned*)&b;
        ((uint2*)g_kh)[j] = o;
    }
    if (i4 < B_) g_rowmax[i4] = 0u;
}

// ---------------- kernel 2: fp16 HMMA GEMM (fp16 accum) -----------------------
// CTA tile 128x128, K=512 in 8 chunks of 64 (128B rows). 8 warps 4(M)x2(N).
// R2-proven 2-stage LDG->STS pipeline; fp16 accumulators halve register load.
#define KC 64
#define CHUNK_BYTES 16384            // 128 rows * 128 B (A or B)
#define BUF_BYTES   32768            // A + B per stage
#define SMEM_ALLOC  (2 * BUF_BYTES + 1024)

__device__ __forceinline__ void ldg_chunk(uint4* st, const __half* Ag,
                                          const __half* Bg, int k0, int tid) {
    #pragma unroll
    for (int j = 0; j < 4; j++) {
        int u = j * 256 + tid;
        st[j] = *(const uint4*)(Ag + (size_t)(u >> 3) * D_ + k0 + (u & 7) * 8);
    }
    #pragma unroll
    for (int j = 0; j < 4; j++) {
        int u = j * 256 + tid;
        st[4 + j] = *(const uint4*)(Bg + (size_t)(u >> 3) * D_ + k0 + (u & 7) * 8);
    }
}

__device__ __forceinline__ void sts_chunk(char* buf, const uint4* st, int tid) {
    #pragma unroll
    for (int j = 0; j < 4; j++) {
        int u = j * 256 + tid;
        uint32_t off = SW128((uint32_t)((u >> 3) * 128 + (u & 7) * 16));
        *(uint4*)(buf + off) = st[j];
    }
    #pragma unroll
    for (int j = 0; j < 4; j++) {
        int u = j * 256 + tid;
        uint32_t off = SW128((uint32_t)((u >> 3) * 128 + (u & 7) * 16));
        *(uint4*)(buf + CHUNK_BYTES + off) = st[4 + j];
    }
}

__global__ void __launch_bounds__(256, 2) gemm_kernel(const float* __restrict__ logt) {
    extern __shared__ char smraw[];
    uint32_t sbr = smem_u32(smraw);
    uint32_t sb = (sbr + 1023u) & ~1023u;
    char* smem = smraw + (sb - sbr);

    int tid = threadIdx.x;
    int wid = tid >> 5, lane = tid & 31;
    int wm = wid >> 1, wn = wid & 1;
    int mt = blockIdx.x & 7;           // 8 M tiles, consecutive blocks share keys tile
    int nt = blockIdx.x >> 3;          // 512 N tiles
    int q0 = mt * 128, c0 = nt * 128;

    const __half* Ag = g_xh + (size_t)q0 * D_;
    const __half* Bg = g_kh + (size_t)c0 * D_;

    uint32_t acc[2][8][2];
    #pragma unroll
    for (int t = 0; t < 2; t++)
        #pragma unroll
        for (int n = 0; n < 8; n++) { acc[t][n][0] = 0u; acc[t][n][1] = 0u; }

    uint4 st[8];
    ldg_chunk(st, Ag, Bg, 0, tid);
    sts_chunk(smem, st, tid);
    __syncthreads();

    // ldmatrix lane address components
    int aRow = wm * 32 + ((lane >> 3) & 1) * 8 + (lane & 7);
    uint32_t aColB = (uint32_t)((lane >> 4) * 16);
    int bm = lane >> 3;
    int bRowIn = (bm >> 1) * 8 + (lane & 7);
    uint32_t bColB = (uint32_t)((bm & 1) * 16);

    #pragma unroll 1
    for (int i = 0; i < 8; i++) {
        if (i < 7) ldg_chunk(st, Ag, Bg, (i + 1) * KC, tid);

        uint32_t bufA = sb + (i & 1) * BUF_BYTES;
        uint32_t bufB = bufA + CHUNK_BYTES;
        #pragma unroll
        for (int ks = 0; ks < 4; ks++) {
            uint32_t kb = (uint32_t)(ks * 32);
            uint32_t a[2][4];
            #pragma unroll
            for (int t = 0; t < 2; t++) {
                uint32_t off = (uint32_t)((aRow + t * 16) * 128) + kb + aColB;
                ldsm4(a[t][0], a[t][1], a[t][2], a[t][3], bufA + SW128(off));
            }
            #pragma unroll
            for (int p = 0; p < 4; p++) {
                uint32_t b0, b1, b2, b3;
                uint32_t off = (uint32_t)((wn * 64 + p * 16 + bRowIn) * 128) + kb + bColB;
                ldsm4(b0, b1, b2, b3, bufB + SW128(off));
                #pragma unroll
                for (int t = 0; t < 2; t++) {
                    mma16816h(acc[t][p * 2 + 0], a[t], b0, b1);
                    mma16816h(acc[t][p * 2 + 1], a[t], b2, b3);
                }
            }
        }
        __syncthreads();
        if (i < 7) {
            sts_chunk(smem + ((i + 1) & 1) * BUF_BYTES, st, tid);
            __syncthreads();
        }
    }

    // epilogue: ws = score * inv_t (fp32 math), fp16 store + rowmax atomics
    float inv_t = __expf(-logt[0]);
    int g = lane >> 2, tig = lane & 3;
    #pragma unroll
    for (int t = 0; t < 2; t++) {
        #pragma unroll
        for (int h = 0; h < 2; h++) {       // h = accumulator register = row group
            int q = q0 + wm * 32 + t * 16 + h * 8 + g;
            __half* dst = g_ws + (size_t)q * C_ + c0 + wn * 64;
            float lmax = -3.4e38f;
            #pragma unroll
            for (int n = 0; n < 8; n++) {
                __half2 hv = *(__half2*)&acc[t][n][h];
                float v0 = __low2float(hv) * inv_t;
                float v1 = __high2float(hv) * inv_t;
                lmax = fmaxf(lmax, fmaxf(v0, v1));
                *(__half2*)(dst + n * 8 + tig * 2) = __floats2half2_rn(v0, v1);
            }
            lmax = fmaxf(lmax, __shfl_xor_sync(0xffffffffu, lmax, 1));
            lmax = fmaxf(lmax, __shfl_xor_sync(0xffffffffu, lmax, 2));
            if (tig == 0) atomicMax(&g_rowmax[q], fenc(lmax));
        }
    }
}

// ---------------- kernel 3: select + exact fp32 softmax + gather ----------------
#define CAP 4096
__global__ void __launch_bounds__(256) sel_kernel(
    const float* __restrict__ x, const float* __restrict__ keys,
    const float* __restrict__ values, const float* __restrict__ logt,
    float* __restrict__ out)
{
    __shared__ float xs[D_];
    __shared__ int   cidx[CAP];
    __shared__ float cw[CAP];
    __shared__ float red[256];
    __shared__ int   cnt;

    int q = blockIdx.x;
    int tid = threadIdx.x;
    float inv_t = __expf(-logt[0]);

    for (int d = tid; d < D_; d += 256) xs[d] = x[(size_t)q * D_ + d];
    if (tid == 0) cnt = 0;
    __syncthreads();

    float mx = fdec(g_rowmax[q]);
    // 16.5 softmax tail + fp16 storage + fp16-accum GEMM error (ws units)
    float thr = mx - (16.5f + 0.001f * fabsf(mx) + 0.8f * inv_t);

    const uint4* wrow = (const uint4*)(g_ws + (size_t)q * C_);
    #pragma unroll 1
    for (int j = 0; j < 32; j++) {
        int idx4 = j * 256 + tid;
        union { uint4 v; __half2 h[4]; } u;
        u.v = __ldg(wrow + idx4);
        int cbase = idx4 * 8;
        #pragma unroll
        for (int e = 0; e < 4; e++) {
            float f0 = __low2float(u.h[e]);
            float f1 = __high2float(u.h[e]);
            if (f0 > thr) { int p = atomicAdd(&cnt, 1); if (p < CAP) cidx[p] = cbase + e * 2; }
            if (f1 > thr) { int p = atomicAdd(&cnt, 1); if (p < CAP) cidx[p] = cbase + e * 2 + 1; }
        }
    }
    __syncthreads();
    int n = min(cnt, CAP);

    // deterministic order (typical n ~ 35)
    if (tid == 0 && n <= 1024) {
        for (int a = 1; a < n; a++) {
            int key = cidx[a]; int bb = a - 1;
            while (bb >= 0 && cidx[bb] > key) { cidx[bb + 1] = cidx[bb]; bb--; }
            cidx[bb + 1] = key;
        }
    }
    __syncthreads();

    // exact fp32 ws for selected candidates (one warp per candidate)
    int w = tid >> 5, lane = tid & 31;
    for (int i = w; i < n; i += 8) {
        const float* kr = keys + (size_t)cidx[i] * D_;
        float s = 0.f;
        #pragma unroll
        for (int kk = 0; kk < 16; kk++) s += xs[lane + kk * 32] * __ldg(kr + lane + kk * 32);
        #pragma unroll
        for (int o = 16; o; o >>= 1) s += __shfl_xor_sync(0xffffffffu, s, o);
        if (lane == 0) cw[i] = s * inv_t;
    }
    __syncthreads();

    // exact max over selected
    float lm = -3.4e38f;
    for (int i = tid; i < n; i += 256) lm = fmaxf(lm, cw[i]);
    red[tid] = lm; __syncthreads();
    for (int s2 = 128; s2; s2 >>= 1) { if (tid < s2) red[tid] = fmaxf(red[tid], red[tid + s2]); __syncthreads(); }
    float m = red[0]; __syncthreads();

    // exp + sum
    float ls = 0.f;
    for (int i = tid; i < n; i += 256) { float e = __expf(cw[i] - m); cw[i] = e; ls += e; }
    red[tid] = ls; __syncthreads();
    for (int s2 = 128; s2; s2 >>= 1) { if (tid < s2) red[tid] += red[tid + s2]; __syncthreads(); }
    float invS = 1.0f / red[0]; __syncthreads();

    // weighted gather of values
    float a0 = 0.f, a1 = 0.f;
    int d0 = tid, d1 = tid + 256;
    #pragma unroll 4
    for (int i = 0; i < n; i++) {
        float wv = cw[i];
        const float* vr = values + (size_t)cidx[i] * D_;
        a0 += wv * __ldg(vr + d0);
        a1 += wv * __ldg(vr + d1);
    }
    out[(size_t)q * D_ + d0] = a0 * invS;
    out[(size_t)q * D_ + d1] = a1 * invS;
}

// ---------------- launch ----------------
extern "C" void kernel_launch(void* const* d_in, const int* in_sizes, int n_in,
                              void* d_out, int out_size) {
    const float* x      = (const float*)d_in[0];
    const float* keys   = (const float*)d_in[1];
    const float* values = (const float*)d_in[2];
    const float* logt   = (const float*)d_in[3];
    float* out = (float*)d_out;

    static bool attr_done = false;
    if (!attr_done) {
        cudaFuncSetAttribute(gemm_kernel, cudaFuncAttributeMaxDynamicSharedMemorySize, SMEM_ALLOC);
        attr_done = true;
    }

    const int conv_blocks = (int)(((size_t)B_ * D_ / 4 + (size_t)C_ * D_ / 4 + 255) / 256);
    conv_kernel<<<conv_blocks, 256>>>(x, keys);
    gemm_kernel<<<(B_ / 128) * (C_ / 128), 256, SMEM_ALLOC>>>(logt);
    sel_kernel<<<B_, 256>>>(x, keys, values, logt, out);
}